// round 1
// baseline (speedup 1.0000x reference)
#include <cuda_runtime.h>

// ---------------------------------------------------------------------------
// Scratch (allocation-free rule: __device__ globals)
// ---------------------------------------------------------------------------
static __device__ float g_Wm[64 * 64];
// y[bi][co][h][w], bi = b*64 + i, 512*16*62*62 floats (~126 MB)
static __device__ float g_y[512u * 16u * 62u * 62u];

// ---------------------------------------------------------------------------
// Kernel 1: reconstruct TT matrix W[64][64] from cores
// Wm[(i1 i2 i3),(j1 j2 j3)] = sum_{r1,r2} c0[0,i1,j1,r1] c1[r1,i2,j2,r2] c2[r2,i3,j3,0]
// ---------------------------------------------------------------------------
__global__ void wm_kernel(const float* __restrict__ c0p,
                          const float* __restrict__ c1p,
                          const float* __restrict__ c2p) {
    __shared__ float s0[128], s1[1024], s2[128];
    for (int i = threadIdx.x; i < 128; i += blockDim.x) s0[i] = c0p[i];
    for (int i = threadIdx.x; i < 1024; i += blockDim.x) s1[i] = c1p[i];
    for (int i = threadIdx.x; i < 128; i += blockDim.x) s2[i] = c2p[i];
    __syncthreads();
    for (int e = threadIdx.x; e < 4096; e += blockDim.x) {
        int i = e >> 6, j = e & 63;
        int i1 = i >> 4, i2 = (i >> 2) & 3, i3 = i & 3;
        int j1 = j >> 4, j2 = (j >> 2) & 3, j3 = j & 3;
        float s = 0.f;
        #pragma unroll
        for (int r1 = 0; r1 < 8; ++r1) {
            float a = s0[(i1 * 4 + j1) * 8 + r1];
            float t = 0.f;
            #pragma unroll
            for (int r2 = 0; r2 < 8; ++r2)
                t += s1[((r1 * 4 + i2) * 4 + j2) * 8 + r2] * s2[(r2 * 4 + i3) * 4 + j3];
            s = fmaf(a, t, s);
        }
        g_Wm[e] = s;
    }
}

// ---------------------------------------------------------------------------
// Kernel 2: 16->16 ch 3x3 VALID conv over 512 images of 64x64.
// grid.x = 512 * 9 strips (7 output rows each). 224 threads:
//   thread = (cohalf in {0,1}, hh in [0,7), wg in [0,16))  -> 8 co x 4 w regs
// ---------------------------------------------------------------------------
__global__ __launch_bounds__(224) void conv_kernel(const float* __restrict__ x,
                                                   const float* __restrict__ ker) {
    __shared__ __align__(16) float xs[16][9][68];     // 39168 B, cols 64..67 zero pad
    __shared__ __align__(16) float ks[16][3][3][16];  // [c_in][kh][kw][c_out], 9216 B

    int bi = blockIdx.x / 9;
    int strip = blockIdx.x % 9;
    int r0 = strip * 7;
    int tid = threadIdx.x;

    // kernel: flat input is [co][cin][kh][kw]
    for (int idx = tid; idx < 2304; idx += 224) {
        int co = idx / 144, rem = idx % 144;
        int cc = rem / 9, kk = rem % 9;
        ks[cc][kk / 3][kk % 3][co] = ker[idx];
    }
    // input rows r0 .. r0+8 (clamped), all 16 channels
    const float* xb = x + (size_t)bi * (16 * 64 * 64);
    for (int idx = tid; idx < 16 * 9 * 68; idx += 224) {
        int w = idx % 68;
        int rr = (idx / 68) % 9;
        int cc = idx / (68 * 9);
        int rg = r0 + rr; if (rg > 63) rg = 63;
        xs[cc][rr][w] = (w < 64) ? xb[(cc * 64 + rg) * 64 + w] : 0.f;
    }
    __syncthreads();

    int cohalf = tid / 112;
    int hh = (tid % 112) / 16;
    int wg = tid % 16;
    int w0 = wg * 4;
    int co0 = cohalf * 8;

    float acc[8][4];
    #pragma unroll
    for (int c = 0; c < 8; ++c)
        #pragma unroll
        for (int p = 0; p < 4; ++p) acc[c][p] = 0.f;

    #pragma unroll 1
    for (int cc = 0; cc < 16; ++cc) {
        #pragma unroll
        for (int kh = 0; kh < 3; ++kh) {
            float kr[3][8];
            #pragma unroll
            for (int kw = 0; kw < 3; ++kw) {
                float4 a  = *reinterpret_cast<const float4*>(&ks[cc][kh][kw][co0]);
                float4 bq = *reinterpret_cast<const float4*>(&ks[cc][kh][kw][co0 + 4]);
                kr[kw][0] = a.x;  kr[kw][1] = a.y;  kr[kw][2] = a.z;  kr[kw][3] = a.w;
                kr[kw][4] = bq.x; kr[kw][5] = bq.y; kr[kw][6] = bq.z; kr[kw][7] = bq.w;
            }
            const float* xrow = &xs[cc][hh + kh][w0];
            float4 xa = *reinterpret_cast<const float4*>(xrow);
            float2 xv2 = *reinterpret_cast<const float2*>(xrow + 4);
            float xr[6] = {xa.x, xa.y, xa.z, xa.w, xv2.x, xv2.y};
            #pragma unroll
            for (int kw = 0; kw < 3; ++kw)
                #pragma unroll
                for (int p = 0; p < 4; ++p) {
                    float xv = xr[p + kw];
                    #pragma unroll
                    for (int c = 0; c < 8; ++c)
                        acc[c][p] = fmaf(xv, kr[kw][c], acc[c][p]);
                }
        }
    }
    __syncthreads();

    // stage into smem (reuse xs region: 16*7*64 = 7168 floats < 9792) so the
    // global store is fully coalesced along w.
    float (*st)[7][64] = reinterpret_cast<float (*)[7][64]>(&xs[0][0][0]);
    #pragma unroll
    for (int c = 0; c < 8; ++c)
        #pragma unroll
        for (int p = 0; p < 4; ++p)
            st[co0 + c][hh][w0 + p] = acc[c][p];
    __syncthreads();

    float* yb = g_y + (size_t)bi * (16 * 62 * 62);
    for (int idx = tid; idx < 16 * 7 * 62; idx += 224) {
        int w = idx % 62;
        int hhh = (idx / 62) % 7;
        int co = idx / (62 * 7);
        int h = r0 + hhh;
        if (h < 62) yb[(co * 62 + h) * 62 + w] = st[co][hhh][w];
    }
}

// ---------------------------------------------------------------------------
// Kernel 3: out[b][co][p][j] = sum_i y[b*64+i][co][p] * Wm[i][j] + bias[j]
// grid = (31 pixel-chunks of 128, 16 co, 8 b); 256 threads:
//   thread = (pg in [0,16) x 8 pixels, jg in [0,16) x 4 j)
// ---------------------------------------------------------------------------
__global__ __launch_bounds__(256) void mix_kernel(const float* __restrict__ bias,
                                                  float* __restrict__ out) {
    __shared__ __align__(16) float Ysm[64][128];  // 32768 B
    __shared__ __align__(16) float Wsm[64][64];   // 16384 B  (total = 48 KB exactly)

    int p0 = blockIdx.x * 128;
    int co = blockIdx.y;
    int b  = blockIdx.z;
    int tid = threadIdx.x;

    for (int idx = tid; idx < 4096; idx += 256)
        (&Wsm[0][0])[idx] = g_Wm[idx];
    for (int idx = tid; idx < 64 * 128; idx += 256) {
        int i = idx >> 7;
        int p = idx & 127;
        int pp = p0 + p;
        Ysm[i][p] = (pp < 3844)
            ? g_y[(((size_t)(b * 64 + i) * 16 + co) * 3844) + pp]
            : 0.f;
    }
    __syncthreads();

    int jg = tid & 15;
    int pg = tid >> 4;
    int j0 = jg * 4;
    int pb = pg * 8;

    float acc[4][8];
    #pragma unroll
    for (int j = 0; j < 4; ++j)
        #pragma unroll
        for (int p = 0; p < 8; ++p) acc[j][p] = 0.f;

    #pragma unroll 4
    for (int k = 0; k < 64; ++k) {
        float4 wv = *reinterpret_cast<const float4*>(&Wsm[k][j0]);
        float4 y0 = *reinterpret_cast<const float4*>(&Ysm[k][pb]);
        float4 y1 = *reinterpret_cast<const float4*>(&Ysm[k][pb + 4]);
        float yv[8] = {y0.x, y0.y, y0.z, y0.w, y1.x, y1.y, y1.z, y1.w};
        float wj[4] = {wv.x, wv.y, wv.z, wv.w};
        #pragma unroll
        for (int p = 0; p < 8; ++p)
            #pragma unroll
            for (int j = 0; j < 4; ++j)
                acc[j][p] = fmaf(yv[p], wj[j], acc[j][p]);
    }

    float bv0 = bias[j0 + 0], bv1 = bias[j0 + 1], bv2 = bias[j0 + 2], bv3 = bias[j0 + 3];
    size_t rowbase = (size_t)(b * 16 + co) * 3844;
    #pragma unroll
    for (int p = 0; p < 8; ++p) {
        int pp = p0 + pb + p;
        if (pp < 3844) {
            float4 v = make_float4(acc[0][p] + bv0, acc[1][p] + bv1,
                                   acc[2][p] + bv2, acc[3][p] + bv3);
            *reinterpret_cast<float4*>(&out[(rowbase + pp) * 64 + j0]) = v;
        }
    }
}

// ---------------------------------------------------------------------------
extern "C" void kernel_launch(void* const* d_in, const int* in_sizes, int n_in,
                              void* d_out, int out_size) {
    const float* x    = (const float*)d_in[0];
    const float* ker  = (const float*)d_in[1];
    const float* c0   = (const float*)d_in[2];
    const float* c1   = (const float*)d_in[3];
    const float* c2   = (const float*)d_in[4];
    const float* bias = (const float*)d_in[5];
    float* out = (float*)d_out;

    wm_kernel<<<1, 256>>>(c0, c1, c2);
    conv_kernel<<<512 * 9, 224>>>(x, ker);
    mix_kernel<<<dim3(31, 16, 8), 256>>>(bias, out);
}

// round 2
// speedup vs baseline: 1.1759x; 1.1759x over previous
#include <cuda_runtime.h>

typedef unsigned long long u64;

// ---------------------------------------------------------------------------
// Packed f32x2 helpers (FFMA2: ptxas never emits this from C++; PTX only)
// ---------------------------------------------------------------------------
__device__ __forceinline__ u64 fma2(u64 a, u64 b, u64 c) {
    u64 d;
    asm("fma.rn.f32x2 %0, %1, %2, %3;" : "=l"(d) : "l"(a), "l"(b), "l"(c));
    return d;
}
__device__ __forceinline__ u64 dup2(float v) {
    u64 r;
    asm("mov.b64 %0, {%1, %1};" : "=l"(r) : "f"(v));
    return r;
}
__device__ __forceinline__ void up2(u64 v, float& lo, float& hi) {
    asm("mov.b64 {%0, %1}, %2;" : "=f"(lo), "=f"(hi) : "l"(v));
}

// ---------------------------------------------------------------------------
// Scratch (allocation-free rule: __device__ globals)
// ---------------------------------------------------------------------------
static __device__ float g_Wm[64 * 64];
// y[bi][co][h][w], bi = b*64 + i, 512*16*62*62 floats (~126 MB)
static __device__ float g_y[512u * 16u * 62u * 62u];

// ---------------------------------------------------------------------------
// Kernel 1: 16->16 ch 3x3 VALID conv over 512 images of 64x64.
// grid.x = 512*9 strips (7 output rows each) + 1 extra block that builds the
// TT matrix g_Wm (conv does not depend on it; mix runs after) -> wm is free.
// 224 threads: thread = (cohalf{0,1}, hh[0,7), wg[0,16)) -> 8 co x 4 w regs,
// accumulators packed in co-pairs (f32x2).
// ---------------------------------------------------------------------------
__global__ __launch_bounds__(224) void conv_kernel(const float* __restrict__ x,
                                                   const float* __restrict__ ker,
                                                   const float* __restrict__ c0p,
                                                   const float* __restrict__ c1p,
                                                   const float* __restrict__ c2p) {
    __shared__ __align__(16) float xs[16][9][68];     // 39168 B
    __shared__ __align__(16) float ks[16][3][3][16];  // [cin][kh][kw][co], 9216 B

    int tid = threadIdx.x;

    if (blockIdx.x == 512 * 9) {
        // ---- TT-matrix reconstruction block (hidden under conv wave) ----
        float* s0 = &xs[0][0][0];        // 128
        float* s1 = s0 + 128;            // 1024
        float* s2 = s1 + 1024;           // 128
        for (int i = tid; i < 128; i += 224) s0[i] = c0p[i];
        for (int i = tid; i < 1024; i += 224) s1[i] = c1p[i];
        for (int i = tid; i < 128; i += 224) s2[i] = c2p[i];
        __syncthreads();
        for (int e = tid; e < 4096; e += 224) {
            int i = e >> 6, j = e & 63;
            int i1 = i >> 4, i2 = (i >> 2) & 3, i3 = i & 3;
            int j1 = j >> 4, j2 = (j >> 2) & 3, j3 = j & 3;
            float s = 0.f;
            #pragma unroll
            for (int r1 = 0; r1 < 8; ++r1) {
                float a = s0[(i1 * 4 + j1) * 8 + r1];
                float t = 0.f;
                #pragma unroll
                for (int r2 = 0; r2 < 8; ++r2)
                    t += s1[((r1 * 4 + i2) * 4 + j2) * 8 + r2] * s2[(r2 * 4 + i3) * 4 + j3];
                s = fmaf(a, t, s);
            }
            g_Wm[e] = s;
        }
        return;
    }

    int bi = blockIdx.x / 9;
    int strip = blockIdx.x % 9;
    int r0 = strip * 7;

    // kernel: flat input is [co][cin][kh][kw] -> smem [cin][kh][kw][co]
    for (int idx = tid; idx < 2304; idx += 224) {
        int co = idx / 144, rem = idx % 144;
        int cc = rem / 9, kk = rem % 9;
        ks[cc][kk / 3][kk % 3][co] = ker[idx];
    }
    // input rows r0 .. r0+8 (clamped), all 16 channels
    const float* xb = x + (size_t)bi * (16 * 64 * 64);
    for (int idx = tid; idx < 16 * 9 * 68; idx += 224) {
        int w = idx % 68;
        int rr = (idx / 68) % 9;
        int cc = idx / (68 * 9);
        int rg = r0 + rr; if (rg > 63) rg = 63;
        xs[cc][rr][w] = (w < 64) ? xb[(cc * 64 + rg) * 64 + w] : 0.f;
    }
    __syncthreads();

    int cohalf = tid / 112;
    int hh = (tid % 112) / 16;
    int wg = tid % 16;
    int w0 = wg * 4;
    int co0 = cohalf * 8;

    u64 acc2[4][4];  // [co-pair][p]
    #pragma unroll
    for (int cp = 0; cp < 4; ++cp)
        #pragma unroll
        for (int p = 0; p < 4; ++p) acc2[cp][p] = 0ull;

    #pragma unroll 1
    for (int cc = 0; cc < 16; ++cc) {
        #pragma unroll
        for (int kh = 0; kh < 3; ++kh) {
            // kernel weights: co-pairs come pre-packed straight from smem
            u64 kr2[3][4];
            #pragma unroll
            for (int kw = 0; kw < 3; ++kw) {
                ulonglong2 a = *reinterpret_cast<const ulonglong2*>(&ks[cc][kh][kw][co0]);
                ulonglong2 b = *reinterpret_cast<const ulonglong2*>(&ks[cc][kh][kw][co0 + 4]);
                kr2[kw][0] = a.x; kr2[kw][1] = a.y;
                kr2[kw][2] = b.x; kr2[kw][3] = b.y;
            }
            const float* xrow = &xs[cc][hh + kh][w0];
            float4 xa = *reinterpret_cast<const float4*>(xrow);
            float2 xb2 = *reinterpret_cast<const float2*>(xrow + 4);
            u64 xd[6] = {dup2(xa.x), dup2(xa.y), dup2(xa.z),
                         dup2(xa.w), dup2(xb2.x), dup2(xb2.y)};
            #pragma unroll
            for (int kw = 0; kw < 3; ++kw)
                #pragma unroll
                for (int p = 0; p < 4; ++p) {
                    u64 xv = xd[p + kw];
                    #pragma unroll
                    for (int cp = 0; cp < 4; ++cp)
                        acc2[cp][p] = fma2(xv, kr2[kw][cp], acc2[cp][p]);
                }
        }
    }
    __syncthreads();

    // stage into smem (reuse xs region: 16*7*64 = 7168 floats) for coalesced
    // global stores along w.
    float (*st)[7][64] = reinterpret_cast<float (*)[7][64]>(&xs[0][0][0]);
    #pragma unroll
    for (int cp = 0; cp < 4; ++cp)
        #pragma unroll
        for (int p = 0; p < 4; ++p) {
            float lo, hi;
            up2(acc2[cp][p], lo, hi);
            st[co0 + 2 * cp][hh][w0 + p] = lo;
            st[co0 + 2 * cp + 1][hh][w0 + p] = hi;
        }
    __syncthreads();

    float* yb = g_y + (size_t)bi * (16 * 62 * 62);
    for (int idx = tid; idx < 16 * 7 * 62; idx += 224) {
        int w = idx % 62;
        int hhh = (idx / 62) % 7;
        int co = idx / (62 * 7);
        int h = r0 + hhh;
        if (h < 62) yb[(co * 62 + h) * 62 + w] = st[co][hhh][w];
    }
}

// ---------------------------------------------------------------------------
// Kernel 2: out[b][co][p][j] = sum_i y[b*64+i][co][p] * Wm[i][j] + bias[j]
// grid = (31 pixel-chunks of 128, 16 co, 8 b); 256 threads:
//   thread = (pg[0,16) x 8 pixels, jg[0,16) x 4 j), pixel-pair packed f32x2.
// ---------------------------------------------------------------------------
__global__ __launch_bounds__(256) void mix_kernel(const float* __restrict__ bias,
                                                  float* __restrict__ out) {
    __shared__ __align__(16) float Ysm[64][128];  // 32768 B
    __shared__ __align__(16) float Wsm[64][64];   // 16384 B  (48 KB total)

    int p0 = blockIdx.x * 128;
    int co = blockIdx.y;
    int b  = blockIdx.z;
    int tid = threadIdx.x;

    for (int idx = tid; idx < 4096; idx += 256)
        (&Wsm[0][0])[idx] = g_Wm[idx];
    for (int idx = tid; idx < 64 * 128; idx += 256) {
        int i = idx >> 7;
        int p = idx & 127;
        int pp = p0 + p;
        Ysm[i][p] = (pp < 3844)
            ? g_y[(((size_t)(b * 64 + i) * 16 + co) * 3844) + pp]
            : 0.f;
    }
    __syncthreads();

    int jg = tid & 15;
    int pg = tid >> 4;
    int j0 = jg * 4;
    int pb = pg * 8;

    u64 acc2[4][4];  // [j][pixel-pair]
    #pragma unroll
    for (int j = 0; j < 4; ++j)
        #pragma unroll
        for (int q = 0; q < 4; ++q) acc2[j][q] = 0ull;

    #pragma unroll 4
    for (int k = 0; k < 64; ++k) {
        // pixel pairs come pre-packed straight from smem
        ulonglong2 ya = *reinterpret_cast<const ulonglong2*>(&Ysm[k][pb]);
        ulonglong2 yc = *reinterpret_cast<const ulonglong2*>(&Ysm[k][pb + 4]);
        u64 yv[4] = {ya.x, ya.y, yc.x, yc.y};
        float4 wv = *reinterpret_cast<const float4*>(&Wsm[k][j0]);
        u64 wd[4] = {dup2(wv.x), dup2(wv.y), dup2(wv.z), dup2(wv.w)};
        #pragma unroll
        for (int q = 0; q < 4; ++q)
            #pragma unroll
            for (int j = 0; j < 4; ++j)
                acc2[j][q] = fma2(yv[q], wd[j], acc2[j][q]);
    }

    float bv[4] = {bias[j0], bias[j0 + 1], bias[j0 + 2], bias[j0 + 3]};
    size_t rowbase = (size_t)(b * 16 + co) * 3844;
    #pragma unroll
    for (int q = 0; q < 4; ++q) {
        float a0l, a0h, a1l, a1h, a2l, a2h, a3l, a3h;
        up2(acc2[0][q], a0l, a0h);
        up2(acc2[1][q], a1l, a1h);
        up2(acc2[2][q], a2l, a2h);
        up2(acc2[3][q], a3l, a3h);
        int ppl = p0 + pb + 2 * q;
        if (ppl < 3844) {
            float4 v = make_float4(a0l + bv[0], a1l + bv[1], a2l + bv[2], a3l + bv[3]);
            *reinterpret_cast<float4*>(&out[(rowbase + ppl) * 64 + j0]) = v;
        }
        if (ppl + 1 < 3844) {
            float4 v = make_float4(a0h + bv[0], a1h + bv[1], a2h + bv[2], a3h + bv[3]);
            *reinterpret_cast<float4*>(&out[(rowbase + ppl + 1) * 64 + j0]) = v;
        }
    }
}

// ---------------------------------------------------------------------------
extern "C" void kernel_launch(void* const* d_in, const int* in_sizes, int n_in,
                              void* d_out, int out_size) {
    const float* x    = (const float*)d_in[0];
    const float* ker  = (const float*)d_in[1];
    const float* c0   = (const float*)d_in[2];
    const float* c1   = (const float*)d_in[3];
    const float* c2   = (const float*)d_in[4];
    const float* bias = (const float*)d_in[5];
    float* out = (float*)d_out;

    conv_kernel<<<512 * 9 + 1, 224>>>(x, ker, c0, c1, c2);
    mix_kernel<<<dim3(31, 16, 8), 256>>>(bias, out);
}